// round 4
// baseline (speedup 1.0000x reference)
#include <cuda_runtime.h>
#include <cuda_bf16.h>
#include <cstdint>

#define NC  100000
#define NT  100000
#define NNZ 640000
#define D   128
#define CAP 32          // bucket capacity per row (avg 6.4 nnz/row, Poisson)
#define BPT 4           // bucket-kernel entries per thread (MLP)

// ---- device-global scratch (no allocation allowed) ----
__device__ int  g_cnt[NC];            // per-row nnz count
__device__ int  g_bucket[NC * CAP];   // col indices, bucketed by row (~12.8 MB)
__device__ int  g_ovf_cnt;            // overflow entry count
__device__ int2 g_ovf[NNZ];           // overflow (row, col) pairs — worst case

// Phase 1 (fused hist+scatter): each thread handles BPT independent nonzeros
// so BPT atomic->store chains are in flight simultaneously (the R3 version had
// MLP=1 per thread and was latency-bound at 12.6us / issue 4.7%).
__global__ __launch_bounds__(256) void bucket_kernel(
    const int* __restrict__ row, const int* __restrict__ col) {
    const int base = blockIdx.x * (256 * BPT) + threadIdx.x;

    int r[BPT], c[BPT], slot[BPT];
    bool ok[BPT];

    #pragma unroll
    for (int k = 0; k < BPT; ++k) {
        int i = base + k * 256;
        ok[k] = (i < NNZ);
        if (ok[k]) {
            r[k] = __ldg(row + i);
            c[k] = __ldg(col + i);
        }
    }
    // Issue all atomics back-to-back (independent chains).
    #pragma unroll
    for (int k = 0; k < BPT; ++k) {
        if (ok[k]) slot[k] = atomicAdd(&g_cnt[r[k]], 1);
    }
    #pragma unroll
    for (int k = 0; k < BPT; ++k) {
        if (ok[k]) {
            if (slot[k] < CAP) {
                g_bucket[r[k] * CAP + slot[k]] = c[k];
            } else {
                int p = atomicAdd(&g_ovf_cnt, 1);
                g_ovf[p] = make_int2(r[k], c[k]);
            }
        }
    }
}

// Phase 2: one warp per output row. Each lane owns one float4 of the D=128
// row. Lane l preloads bucket col l; shfl-broadcast drives up to 32
// independent float4 gathers; single plain store (covers zero rows too).
__global__ __launch_bounds__(256) void gather_sum_kernel(
    const float4* __restrict__ mat, float4* __restrict__ out) {
    int r    = (blockIdx.x * blockDim.x + threadIdx.x) >> 5;
    int lane = threadIdx.x & 31;
    if (r >= NC) return;

    int n = __ldg(g_cnt + r);
    if (n > CAP) n = CAP;

    int cj = (lane < n) ? __ldg(g_bucket + r * CAP + lane) : 0;

    float4 acc = make_float4(0.f, 0.f, 0.f, 0.f);
    #pragma unroll 8
    for (int j = 0; j < n; ++j) {
        int c = __shfl_sync(0xffffffffu, cj, j);
        float4 v = __ldg(mat + (size_t)c * (D / 4) + lane);
        acc.x += v.x; acc.y += v.y; acc.z += v.z; acc.w += v.w;
    }

    out[(size_t)r * (D / 4) + lane] = acc;
}

// Phase 3: apply overflow entries (expected count: 0) with vector red.add.
// Runs after gather's plain stores, so ordering is safe.
__global__ __launch_bounds__(256) void overflow_kernel(
    const float4* __restrict__ mat, float4* __restrict__ out) {
    int warp  = (blockIdx.x * blockDim.x + threadIdx.x) >> 5;
    int lane  = threadIdx.x & 31;
    int nwarp = (gridDim.x * blockDim.x) >> 5;
    int cnt   = g_ovf_cnt;
    if (cnt > NNZ) cnt = NNZ;
    for (int i = warp; i < cnt; i += nwarp) {
        int2 e = g_ovf[i];
        float4 v = __ldg(mat + (size_t)e.y * (D / 4) + lane);
        float* dst = reinterpret_cast<float*>(out) + (size_t)e.x * D + lane * 4;
        asm volatile(
            "red.global.add.v4.f32 [%0], {%1, %2, %3, %4};"
            :: "l"(dst), "f"(v.x), "f"(v.y), "f"(v.z), "f"(v.w)
            : "memory");
    }
}

extern "C" void kernel_launch(void* const* d_in, const int* in_sizes, int n_in,
                              void* d_out, int out_size) {
    const float4* mat = (const float4*)d_in[0];
    const int*    row = (const int*)d_in[1];
    const int*    col = (const int*)d_in[2];
    float4*       out = (float4*)d_out;

    // Zero the counters via memset nodes (graph-capturable).
    void* cnt_ptr = nullptr;
    void* ovf_ptr = nullptr;
    cudaGetSymbolAddress(&cnt_ptr, g_cnt);
    cudaGetSymbolAddress(&ovf_ptr, g_ovf_cnt);
    cudaMemsetAsync(cnt_ptr, 0, (size_t)NC * sizeof(int));
    cudaMemsetAsync(ovf_ptr, 0, sizeof(int));

    const int T = 256;
    const int bucket_blocks = (NNZ + T * BPT - 1) / (T * BPT);   // 625
    bucket_kernel<<<bucket_blocks, T>>>(row, col);

    const long long total_threads = (long long)NC * 32;
    gather_sum_kernel<<<(int)((total_threads + T - 1) / T), T>>>(mat, out);

    overflow_kernel<<<16, T>>>(mat, out);
}